// round 6
// baseline (speedup 1.0000x reference)
#include <cuda_runtime.h>
#include <math.h>

#define C_IN 768
#define DDIM 8
#define LDIM 8
#define NTOK_MAX 65536

#define K1_THREADS 256
#define TILE_TOK 256
#define CHUNK 16
#define NCHUNK (C_IN / CHUNK)   // 48
#define ZPITCH 20  // floats; pitch % 8 == 4 -> conflict-free per-lane LDS.128

// dynamic smem layout for k_compress: [ Wc | Z0 | Z1 ]
#define SM_WC_FLOATS (C_IN * DDIM)           // 6144 floats = 24 KB
#define SM_Z_FLOATS  (TILE_TOK * ZPITCH)     // 5120 floats = 20 KB
#define K1_DYN_BYTES ((SM_WC_FLOATS + 2 * SM_Z_FLOATS) * 4)  // 65536 B

#define K2_THREADS 192
#define K2_TILE 256

// Scratch (no allocations allowed)
__device__ unsigned long long g_codes[(size_t)NTOK_MAX * DDIM];
__device__ float g_partials[NTOK_MAX / TILE_TOK];

static __device__ __forceinline__ unsigned long long pack2(float lo, float hi) {
    unsigned long long r;
    asm("mov.b64 %0, {%1, %2};" : "=l"(r) : "f"(lo), "f"(hi));
    return r;
}
static __device__ __forceinline__ void unpack2(unsigned long long v, float& lo, float& hi) {
    asm("mov.b64 {%0, %1}, %2;" : "=f"(lo), "=f"(hi) : "l"(v));
}
// Packed fp32x2 FMA (sm_100+): 2 IEEE fp32 FMAs per instruction.
static __device__ __forceinline__ unsigned long long fma2(unsigned long long a,
                                                          unsigned long long b,
                                                          unsigned long long c) {
    unsigned long long d;
    asm("fma.rn.f32x2 %0, %1, %2, %3;" : "=l"(d) : "l"(a), "l"(b), "l"(c));
    return d;
}

// Kernel 1: compress GEMV + gumbel argmax + codes + per-block squared-error partial.
// Thread-per-token; Wc broadcast from shared; z staged via DOUBLE-BUFFERED dynamic
// shared (one barrier per 16-channel chunk; next chunk's LDGs overlap compute).
__global__ void __launch_bounds__(K1_THREADS) k_compress(
    const float* __restrict__ z, const float* __restrict__ u,
    const float* __restrict__ Wc, const float* __restrict__ bc,
    const float* __restrict__ cb, int ntok)
{
    extern __shared__ __align__(16) float dyn[];
    float* sWc = dyn;                          // 24 KB
    float* sZ[2] = { dyn + SM_WC_FLOATS,       // 20 KB
                     dyn + SM_WC_FLOATS + SM_Z_FLOATS };  // 20 KB

    __shared__ float sBC[DDIM];
    __shared__ float sCB[DDIM * LDIM];
    __shared__ float sRed[K1_THREADS / 32];

    const int tid = threadIdx.x;

    for (int i = tid; i < C_IN * DDIM; i += K1_THREADS) sWc[i] = Wc[i];
    if (tid < DDIM) sBC[tid] = bc[tid];
    if (tid < DDIM * LDIM) sCB[tid] = cb[tid];

    const int tok0 = blockIdx.x * TILE_TOK;
    const int mytok = tok0 + tid;

    unsigned long long acc0 = pack2(0.f, 0.f);
    unsigned long long acc1 = acc0, acc2 = acc0, acc3 = acc0;

    const int srow = tid >> 2;         // 0..63
    const int scol = (tid & 3) * 4;    // float4 slot within 16-ch chunk

    // Stage-row global token (clamped once)
    int stok[4];
    #pragma unroll
    for (int it = 0; it < 4; it++) {
        int gt = tok0 + srow + it * 64;
        stok[it] = (gt < ntok) ? gt : (ntok - 1);
    }

    // Prologue: load + stage chunk 0
    #pragma unroll
    for (int it = 0; it < 4; it++) {
        float4 v = *reinterpret_cast<const float4*>(
            &z[(size_t)stok[it] * C_IN + scol]);
        *reinterpret_cast<float4*>(&sZ[0][(srow + it * 64) * ZPITCH + scol]) = v;
    }
    __syncthreads();

    for (int k = 0; k < NCHUNK; k++) {
        const int buf = k & 1;
        // Prefetch chunk k+1 from global while computing chunk k
        float4 pf[4];
        if (k + 1 < NCHUNK) {
            const int c1 = (k + 1) * CHUNK;
            #pragma unroll
            for (int it = 0; it < 4; it++)
                pf[it] = *reinterpret_cast<const float4*>(
                    &z[(size_t)stok[it] * C_IN + c1 + scol]);
        }
        // Compute on chunk k
        const int c0 = k * CHUNK;
        #pragma unroll
        for (int g = 0; g < CHUNK; g += 4) {
            float4 zv = *reinterpret_cast<const float4*>(&sZ[buf][tid * ZPITCH + g]);
            const ulonglong2* wr =
                reinterpret_cast<const ulonglong2*>(&sWc[(c0 + g) * DDIM]);
            float zk[4] = {zv.x, zv.y, zv.z, zv.w};
            #pragma unroll
            for (int kk = 0; kk < 4; kk++) {
                unsigned long long zz = pack2(zk[kk], zk[kk]);
                ulonglong2 wa = wr[kk * 2 + 0];   // Wc[row][0..3] broadcast
                ulonglong2 wb = wr[kk * 2 + 1];   // Wc[row][4..7] broadcast
                acc0 = fma2(zz, wa.x, acc0);
                acc1 = fma2(zz, wa.y, acc1);
                acc2 = fma2(zz, wb.x, acc2);
                acc3 = fma2(zz, wb.y, acc3);
            }
        }
        // Stage chunk k+1 into the other buffer
        if (k + 1 < NCHUNK) {
            #pragma unroll
            for (int it = 0; it < 4; it++)
                *reinterpret_cast<float4*>(
                    &sZ[buf ^ 1][(srow + it * 64) * ZPITCH + scol]) = pf[it];
        }
        __syncthreads();
    }

    float zc[DDIM];
    unpack2(acc0, zc[0], zc[1]);
    unpack2(acc1, zc[2], zc[3]);
    unpack2(acc2, zc[4], zc[5]);
    unpack2(acc3, zc[6], zc[7]);
    #pragma unroll
    for (int d = 0; d < DDIM; d++) zc[d] += sBC[d];

    float err = 0.0f;
    if (mytok < ntok) {
        const float4* u4 = reinterpret_cast<const float4*>(u + (size_t)mytok * DDIM * LDIM);
        #pragma unroll
        for (int d = 0; d < DDIM; d++) {
            float4 ua = u4[d * 2 + 0];
            float4 ub = u4[d * 2 + 1];
            float uv[LDIM] = {ua.x, ua.y, ua.z, ua.w, ub.x, ub.y, ub.z, ub.w};
            float best = -INFINITY;
            int bi = 0;
            // argmax over l of gumbel(u) - |zc - cb|  (== argmax of reference
            // softmax since TAU=1; strict > keeps first index on ties,
            // matching jnp.argmax)
            #pragma unroll
            for (int l = 0; l < LDIM; l++) {
                float la = logf(uv[l] + 1e-10f);
                float gmb = -logf(-la);
                float s = gmb - fabsf(zc[d] - sCB[d * LDIM + l]);
                if (s > best) { best = s; bi = l; }
            }
            float code = sCB[d * LDIM + bi];
            float dd = zc[d] - code;
            err += dd * dd;
            g_codes[(size_t)mytok * DDIM + d] = pack2(code, code);
        }
    }

    // Block-reduce squared error -> per-block partial (no atomics, no init kernel)
    #pragma unroll
    for (int o = 16; o > 0; o >>= 1) err += __shfl_down_sync(0xffffffffu, err, o);
    if ((tid & 31) == 0) sRed[tid >> 5] = err;
    __syncthreads();
    if (tid == 0) {
        float t = 0.f;
        #pragma unroll
        for (int w = 0; w < K1_THREADS / 32; w++) t += sRed[w];
        g_partials[blockIdx.x] = t;
    }
}

// Kernel 2: expand z_q = codes @ We + be.
// Thread owns 4 consecutive channels; We row slices in registers; codes
// broadcast from shared; coalesced STG.128. 4-token unroll for fma2 ILP.
// Block 0 additionally reduces the error partials and writes the scalar.
__global__ void __launch_bounds__(K2_THREADS) k_expand(
    const float* __restrict__ We, const float* __restrict__ be,
    float* __restrict__ out, int ntok, int npart,
    long long erridx, float errinv)
{
    __shared__ __align__(16) unsigned long long sC[K2_TILE * DDIM];  // 16 KB
    const int tid = threadIdx.x;
    const int c0 = tid * 4;

    ulonglong2 wv[DDIM];
    #pragma unroll
    for (int d = 0; d < DDIM; d++)
        wv[d] = *reinterpret_cast<const ulonglong2*>(&We[d * C_IN + c0]);
    ulonglong2 bev = *reinterpret_cast<const ulonglong2*>(&be[c0]);

    const int tok0 = blockIdx.x * K2_TILE;
    for (int i = tid; i < K2_TILE * DDIM; i += K2_THREADS)
        sC[i] = g_codes[(size_t)tok0 * DDIM + i];
    __syncthreads();

    int tmax = ntok - tok0;
    if (tmax > K2_TILE) tmax = K2_TILE;

    int t = 0;
    for (; t + 4 <= tmax; t += 4) {
        unsigned long long a[4][2];
        #pragma unroll
        for (int j = 0; j < 4; j++) { a[j][0] = bev.x; a[j][1] = bev.y; }
        #pragma unroll
        for (int d = 0; d < DDIM; d++) {
            #pragma unroll
            for (int j = 0; j < 4; j++) {
                unsigned long long cd = sC[(t + j) * DDIM + d];  // broadcast
                a[j][0] = fma2(cd, wv[d].x, a[j][0]);
                a[j][1] = fma2(cd, wv[d].y, a[j][1]);
            }
        }
        #pragma unroll
        for (int j = 0; j < 4; j++) {
            float4 o;
            unpack2(a[j][0], o.x, o.y);
            unpack2(a[j][1], o.z, o.w);
            *reinterpret_cast<float4*>(&out[(size_t)(tok0 + t + j) * C_IN + c0]) = o;
        }
    }
    for (; t < tmax; t++) {
        unsigned long long a0 = bev.x, a1 = bev.y;
        #pragma unroll
        for (int d = 0; d < DDIM; d++) {
            unsigned long long cd = sC[t * DDIM + d];
            a0 = fma2(cd, wv[d].x, a0);
            a1 = fma2(cd, wv[d].y, a1);
        }
        float4 o;
        unpack2(a0, o.x, o.y);
        unpack2(a1, o.z, o.w);
        *reinterpret_cast<float4*>(&out[(size_t)(tok0 + t) * C_IN + c0]) = o;
    }

    // Block 0, warp 0: finalize quantization_error scalar
    if (blockIdx.x == 0 && tid < 32 && erridx >= 0) {
        float s = 0.f;
        for (int i = tid; i < npart; i += 32) s += g_partials[i];
        #pragma unroll
        for (int o = 16; o > 0; o >>= 1) s += __shfl_down_sync(0xffffffffu, s, o);
        if (tid == 0) out[erridx] = s * errinv;
    }
}

extern "C" void kernel_launch(void* const* d_in, const int* in_sizes, int n_in,
                              void* d_out, int out_size) {
    const float* z  = (const float*)d_in[0];
    const float* u  = (const float*)d_in[1];
    const float* Wc = (const float*)d_in[2];
    const float* bc = (const float*)d_in[3];
    const float* We = (const float*)d_in[4];
    const float* be = (const float*)d_in[5];
    const float* cb = (const float*)d_in[6];
    // d_in[7] = codebook_mask: all-true here (levels == [8]*8), intentionally unused.
    float* out = (float*)d_out;

    // Raise dynamic smem cap (host attribute set; not an allocation, capture-safe)
    static bool attr_done = false;
    if (!attr_done) {
        cudaFuncSetAttribute(k_compress,
                             cudaFuncAttributeMaxDynamicSharedMemorySize,
                             K1_DYN_BYTES);
        attr_done = true;
    }

    const int ntok = in_sizes[0] / C_IN;  // 65536
    const int g1 = (ntok + TILE_TOK - 1) / TILE_TOK;
    const int g2 = (ntok + K2_TILE - 1) / K2_TILE;

    long long erridx = (out_size > ntok * C_IN) ? (long long)ntok * C_IN : -1;

    k_compress<<<g1, K1_THREADS, K1_DYN_BYTES>>>(z, u, Wc, bc, cb, ntok);
    k_expand<<<g2, K2_THREADS>>>(We, be, out, ntok, g1, erridx,
                                 1.0f / ((float)ntok * (float)DDIM));
}

// round 7
// speedup vs baseline: 1.2534x; 1.2534x over previous
#include <cuda_runtime.h>
#include <math.h>

#define C_IN 768
#define DDIM 8
#define LDIM 8
#define NTOK_MAX 65536

#define K1_THREADS 256
#define K1_TOKS 64              // tokens per compress block (4 lanes/token)
#define NITER (C_IN / 16)       // 48 iters, 4 channels per lane per iter

#define K2_THREADS 192
#define K2_TILE 64              // tokens per expand block -> 1024 blocks

// Scratch (no allocations allowed)
__device__ unsigned long long g_codes[(size_t)NTOK_MAX * DDIM];
__device__ float g_partials[NTOK_MAX / K1_TOKS];

static __device__ __forceinline__ unsigned long long pack2(float lo, float hi) {
    unsigned long long r;
    asm("mov.b64 %0, {%1, %2};" : "=l"(r) : "f"(lo), "f"(hi));
    return r;
}
static __device__ __forceinline__ void unpack2(unsigned long long v, float& lo, float& hi) {
    asm("mov.b64 {%0, %1}, %2;" : "=f"(lo), "=f"(hi) : "l"(v));
}
// Packed fp32x2 FMA (sm_100+): 2 IEEE fp32 FMAs per instruction.
static __device__ __forceinline__ unsigned long long fma2(unsigned long long a,
                                                          unsigned long long b,
                                                          unsigned long long c) {
    unsigned long long d;
    asm("fma.rn.f32x2 %0, %1, %2, %3;" : "=l"(d) : "l"(a), "l"(b), "l"(c));
    return d;
}

// Kernel 1: compress GEMV + gumbel argmax + codes + per-block error partial.
// 4 lanes per token, channels interleaved mod-4 (float4 granular). No smem
// staging of z, no barriers in the mainloop. Weights transposed in shared
// (WcT[d][c]) so per-lane ulonglong2 loads are conflict-free broadcasts.
__global__ void __launch_bounds__(K1_THREADS) k_compress(
    const float* __restrict__ z, const float* __restrict__ u,
    const float* __restrict__ Wc, const float* __restrict__ bc,
    const float* __restrict__ cb, int ntok)
{
    __shared__ __align__(16) float sWcT[DDIM * C_IN];   // 24 KB, transposed
    __shared__ float sBC[DDIM];
    __shared__ float sCB[DDIM * LDIM];
    __shared__ float sRed[K1_THREADS / 32];

    const int tid = threadIdx.x;

    // Build transposed weights once (coalesced global reads)
    for (int i = tid; i < C_IN * DDIM; i += K1_THREADS) {
        int c = i >> 3, d = i & 7;
        sWcT[d * C_IN + c] = Wc[i];
    }
    if (tid < DDIM) sBC[tid] = bc[tid];
    if (tid < DDIM * LDIM) sCB[tid] = cb[tid];
    __syncthreads();

    const int j = tid & 3;                        // lane within token group
    const int mytok = blockIdx.x * K1_TOKS + (tid >> 2);
    const int ltok = (mytok < ntok) ? mytok : (ntok - 1);
    const float* zrow = z + (size_t)ltok * C_IN;

    unsigned long long acc[DDIM];
    #pragma unroll
    for (int d = 0; d < DDIM; d++) acc[d] = pack2(0.f, 0.f);

    // Barrier-free mainloop: 1 LDG.128 + 8 broadcast LDS.128 + 16 fma2 per iter
    #pragma unroll 4
    for (int k = 0; k < NITER; k++) {
        const int c = 16 * k + 4 * j;
        float4 zv = *reinterpret_cast<const float4*>(zrow + c);
        unsigned long long zp01 = pack2(zv.x, zv.y);
        unsigned long long zp23 = pack2(zv.z, zv.w);
        const float* wbase = sWcT + c;
        #pragma unroll
        for (int d = 0; d < DDIM; d++) {
            ulonglong2 wd = *reinterpret_cast<const ulonglong2*>(wbase + d * C_IN);
            acc[d] = fma2(zp01, wd.x, acc[d]);
            acc[d] = fma2(zp23, wd.y, acc[d]);
        }
    }

    // Reduce across the 4 lanes of the token group; lane j keeps d = 2j, 2j+1
    const int d0 = 2 * j, d1 = 2 * j + 1;
    float zc0 = 0.f, zc1 = 0.f;
    #pragma unroll
    for (int d = 0; d < DDIM; d++) {
        float lo, hi;
        unpack2(acc[d], lo, hi);
        float v = lo + hi;
        v += __shfl_xor_sync(0xffffffffu, v, 1);
        v += __shfl_xor_sync(0xffffffffu, v, 2);
        v += sBC[d];
        if (d == d0) zc0 = v;
        if (d == d1) zc1 = v;
    }

    float err = 0.0f;
    if (mytok < ntok) {
        // Lane j handles dims d0,d1: u floats [16j, 16j+16) of the token's 64
        const float4* u4 = reinterpret_cast<const float4*>(
            u + (size_t)mytok * (DDIM * LDIM) + 16 * j);
        float4 ua = u4[0], ub = u4[1], uc = u4[2], ud = u4[3];

        float uv0[LDIM] = {ua.x, ua.y, ua.z, ua.w, ub.x, ub.y, ub.z, ub.w};
        float uv1[LDIM] = {uc.x, uc.y, uc.z, uc.w, ud.x, ud.y, ud.z, ud.w};

        // argmax_l of gumbel(u) - |zc - cb|  (== reference softmax argmax,
        // TAU=1; strict > keeps first index on ties, matching jnp.argmax)
        float best0 = -INFINITY, best1 = -INFINITY;
        float code0 = 0.f, code1 = 0.f;
        #pragma unroll
        for (int l = 0; l < LDIM; l++) {
            float cb0 = sCB[d0 * LDIM + l];
            float cb1 = sCB[d1 * LDIM + l];
            float g0 = -logf(-logf(uv0[l] + 1e-10f));
            float g1 = -logf(-logf(uv1[l] + 1e-10f));
            float s0 = g0 - fabsf(zc0 - cb0);
            float s1 = g1 - fabsf(zc1 - cb1);
            if (s0 > best0) { best0 = s0; code0 = cb0; }
            if (s1 > best1) { best1 = s1; code1 = cb1; }
        }
        float e0 = zc0 - code0, e1 = zc1 - code1;
        err = e0 * e0 + e1 * e1;

        ulonglong2 cw;
        cw.x = pack2(code0, code0);
        cw.y = pack2(code1, code1);
        *reinterpret_cast<ulonglong2*>(&g_codes[(size_t)mytok * DDIM + d0]) = cw;
    }

    // Block-reduce squared error -> per-block partial
    #pragma unroll
    for (int o = 16; o > 0; o >>= 1) err += __shfl_down_sync(0xffffffffu, err, o);
    if ((tid & 31) == 0) sRed[tid >> 5] = err;
    __syncthreads();
    if (tid == 0) {
        float t = 0.f;
        #pragma unroll
        for (int w = 0; w < K1_THREADS / 32; w++) t += sRed[w];
        g_partials[blockIdx.x] = t;
    }
}

// Kernel 2: expand z_q = codes @ We + be.
// Thread owns 4 consecutive channels; We row slices in registers; codes
// broadcast from shared; coalesced STG.128. Small 64-token tiles -> 1024
// blocks for occupancy. Block 0 finalizes the error scalar.
__global__ void __launch_bounds__(K2_THREADS) k_expand(
    const float* __restrict__ We, const float* __restrict__ be,
    float* __restrict__ out, int ntok, int npart,
    long long erridx, float errinv)
{
    __shared__ __align__(16) unsigned long long sC[K2_TILE * DDIM];  // 4 KB
    const int tid = threadIdx.x;
    const int c0 = tid * 4;

    ulonglong2 wv[DDIM];
    #pragma unroll
    for (int d = 0; d < DDIM; d++)
        wv[d] = *reinterpret_cast<const ulonglong2*>(&We[d * C_IN + c0]);
    ulonglong2 bev = *reinterpret_cast<const ulonglong2*>(&be[c0]);

    const int tok0 = blockIdx.x * K2_TILE;
    for (int i = tid; i < K2_TILE * DDIM; i += K2_THREADS)
        sC[i] = g_codes[(size_t)tok0 * DDIM + i];
    __syncthreads();

    int tmax = ntok - tok0;
    if (tmax > K2_TILE) tmax = K2_TILE;

    int t = 0;
    for (; t + 4 <= tmax; t += 4) {
        unsigned long long a[4][2];
        #pragma unroll
        for (int q = 0; q < 4; q++) { a[q][0] = bev.x; a[q][1] = bev.y; }
        #pragma unroll
        for (int d = 0; d < DDIM; d++) {
            #pragma unroll
            for (int q = 0; q < 4; q++) {
                unsigned long long cd = sC[(t + q) * DDIM + d];  // broadcast
                a[q][0] = fma2(cd, wv[d].x, a[q][0]);
                a[q][1] = fma2(cd, wv[d].y, a[q][1]);
            }
        }
        #pragma unroll
        for (int q = 0; q < 4; q++) {
            float4 o;
            unpack2(a[q][0], o.x, o.y);
            unpack2(a[q][1], o.z, o.w);
            *reinterpret_cast<float4*>(&out[(size_t)(tok0 + t + q) * C_IN + c0]) = o;
        }
    }
    for (; t < tmax; t++) {
        unsigned long long a0 = bev.x, a1 = bev.y;
        #pragma unroll
        for (int d = 0; d < DDIM; d++) {
            unsigned long long cd = sC[t * DDIM + d];
            a0 = fma2(cd, wv[d].x, a0);
            a1 = fma2(cd, wv[d].y, a1);
        }
        float4 o;
        unpack2(a0, o.x, o.y);
        unpack2(a1, o.z, o.w);
        *reinterpret_cast<float4*>(&out[(size_t)(tok0 + t) * C_IN + c0]) = o;
    }

    // Block 0, warp 0: finalize quantization_error scalar
    if (blockIdx.x == 0 && tid < 32 && erridx >= 0) {
        float s = 0.f;
        for (int i = tid; i < npart; i += 32) s += g_partials[i];
        #pragma unroll
        for (int o = 16; o > 0; o >>= 1) s += __shfl_down_sync(0xffffffffu, s, o);
        if (tid == 0) out[erridx] = s * errinv;
    }
}

extern "C" void kernel_launch(void* const* d_in, const int* in_sizes, int n_in,
                              void* d_out, int out_size) {
    const float* z  = (const float*)d_in[0];
    const float* u  = (const float*)d_in[1];
    const float* Wc = (const float*)d_in[2];
    const float* bc = (const float*)d_in[3];
    const float* We = (const float*)d_in[4];
    const float* be = (const float*)d_in[5];
    const float* cb = (const float*)d_in[6];
    // d_in[7] = codebook_mask: all-true here (levels == [8]*8), intentionally unused.
    float* out = (float*)d_out;

    const int ntok = in_sizes[0] / C_IN;  // 65536
    const int g1 = (ntok + K1_TOKS - 1) / K1_TOKS;   // 1024
    const int g2 = (ntok + K2_TILE - 1) / K2_TILE;   // 1024

    long long erridx = (out_size > ntok * C_IN) ? (long long)ntok * C_IN : -1;

    k_compress<<<g1, K1_THREADS>>>(z, u, Wc, bc, cb, ntok);
    k_expand<<<g2, K2_THREADS>>>(We, be, out, ntok, g1, erridx,
                                 1.0f / ((float)ntok * (float)DDIM));
}

// round 8
// speedup vs baseline: 1.4758x; 1.1774x over previous
#include <cuda_runtime.h>
#include <math.h>

#define C_IN 768
#define DDIM 8
#define LDIM 8

#define THREADS 256
#define TILE 64                 // tokens per block (4 lanes/token in phase 1)
#define NITER (C_IN / 16)       // 48 iters, 4 channels per lane per iter
#define EXP_THREADS 192         // phase-2 channel owners (192*4 = 768)

// Scratch (no allocations allowed)
__device__ float g_partials[4096];
__device__ unsigned int g_done = 0;   // self-resetting via atomicInc wrap

static __device__ __forceinline__ unsigned long long pack2(float lo, float hi) {
    unsigned long long r;
    asm("mov.b64 %0, {%1, %2};" : "=l"(r) : "f"(lo), "f"(hi));
    return r;
}
static __device__ __forceinline__ void unpack2(unsigned long long v, float& lo, float& hi) {
    asm("mov.b64 {%0, %1}, %2;" : "=f"(lo), "=f"(hi) : "l"(v));
}
// Packed fp32x2 FMA (sm_100+): 2 IEEE fp32 FMAs per instruction.
static __device__ __forceinline__ unsigned long long fma2(unsigned long long a,
                                                          unsigned long long b,
                                                          unsigned long long c) {
    unsigned long long d;
    asm("fma.rn.f32x2 %0, %1, %2, %3;" : "=l"(d) : "l"(a), "l"(b), "l"(c));
    return d;
}

// Fused kernel: per block of 64 tokens —
//   Phase 1: compress GEMV (4 lanes/token, barrier-free) + gumbel argmax,
//            codes -> shared, squared-error partial -> global.
//   Phase 2: expand z_q = codes @ We + be straight from shared, coalesced STG.
//   Tail:    deterministic last-block reduction of error partials.
__global__ void __launch_bounds__(THREADS) k_fused(
    const float* __restrict__ z, const float* __restrict__ u,
    const float* __restrict__ Wc, const float* __restrict__ bc,
    const float* __restrict__ We, const float* __restrict__ be,
    const float* __restrict__ cb,
    float* __restrict__ out, int ntok, int nblk,
    long long erridx, float errinv)
{
    __shared__ __align__(16) float sWcT[DDIM * C_IN];            // 24 KB transposed
    __shared__ __align__(16) unsigned long long sC[TILE * DDIM]; // 4 KB (code,code)
    __shared__ float sBC[DDIM];
    __shared__ float sCB[DDIM * LDIM];
    __shared__ float sRed[THREADS / 32];
    __shared__ unsigned int sLast;

    const int tid = threadIdx.x;

    // Stage transposed compress weights (coalesced global reads)
    for (int i = tid; i < C_IN * DDIM; i += THREADS) {
        int c = i >> 3, d = i & 7;
        sWcT[d * C_IN + c] = Wc[i];
    }
    if (tid < DDIM) sBC[tid] = bc[tid];
    if (tid < DDIM * LDIM) sCB[tid] = cb[tid];
    __syncthreads();

    // ---------------- Phase 1: compress ----------------
    const int j = tid & 3;                         // lane within token quad
    const int trow = tid >> 2;                     // 0..63 local token
    const int mytok = blockIdx.x * TILE + trow;
    const int ltok = (mytok < ntok) ? mytok : (ntok - 1);
    const float* zrow = z + (size_t)ltok * C_IN;

    unsigned long long acc[DDIM];
    #pragma unroll
    for (int d = 0; d < DDIM; d++) acc[d] = pack2(0.f, 0.f);

    // Barrier-free mainloop: 1 LDG.128 + 8 broadcast LDS.128 + 16 fma2 / iter
    #pragma unroll 4
    for (int k = 0; k < NITER; k++) {
        const int c = 16 * k + 4 * j;
        float4 zv = *reinterpret_cast<const float4*>(zrow + c);
        unsigned long long zp01 = pack2(zv.x, zv.y);
        unsigned long long zp23 = pack2(zv.z, zv.w);
        const float* wbase = sWcT + c;
        #pragma unroll
        for (int d = 0; d < DDIM; d++) {
            ulonglong2 wd = *reinterpret_cast<const ulonglong2*>(wbase + d * C_IN);
            acc[d] = fma2(zp01, wd.x, acc[d]);
            acc[d] = fma2(zp23, wd.y, acc[d]);
        }
    }

    // Reduce across the 4 lanes of the quad; lane j keeps dims 2j, 2j+1
    const int d0 = 2 * j, d1 = 2 * j + 1;
    float zc0 = 0.f, zc1 = 0.f;
    #pragma unroll
    for (int d = 0; d < DDIM; d++) {
        float lo, hi;
        unpack2(acc[d], lo, hi);
        float v = lo + hi;
        v += __shfl_xor_sync(0xffffffffu, v, 1);
        v += __shfl_xor_sync(0xffffffffu, v, 2);
        v += sBC[d];
        if (d == d0) zc0 = v;
        if (d == d1) zc1 = v;
    }

    float err = 0.0f;
    {
        // Lane j handles dims d0,d1: u floats [16j, 16j+16) of the token's 64
        const float4* u4 = reinterpret_cast<const float4*>(
            u + (size_t)ltok * (DDIM * LDIM) + 16 * j);
        float4 ua = u4[0], ub = u4[1], uc = u4[2], ud = u4[3];
        float uv0[LDIM] = {ua.x, ua.y, ua.z, ua.w, ub.x, ub.y, ub.z, ub.w};
        float uv1[LDIM] = {uc.x, uc.y, uc.z, uc.w, ud.x, ud.y, ud.z, ud.w};

        // argmax_l of gumbel(u) - |zc - cb| (== reference softmax argmax,
        // TAU=1; strict > keeps first index on ties, matching jnp.argmax)
        float best0 = -INFINITY, best1 = -INFINITY;
        float code0 = 0.f, code1 = 0.f;
        #pragma unroll
        for (int l = 0; l < LDIM; l++) {
            float cbv0 = sCB[d0 * LDIM + l];
            float cbv1 = sCB[d1 * LDIM + l];
            float g0 = -logf(-logf(uv0[l] + 1e-10f));
            float g1 = -logf(-logf(uv1[l] + 1e-10f));
            float s0 = g0 - fabsf(zc0 - cbv0);
            float s1 = g1 - fabsf(zc1 - cbv1);
            if (s0 > best0) { best0 = s0; code0 = cbv0; }
            if (s1 > best1) { best1 = s1; code1 = cbv1; }
        }
        if (mytok < ntok) {
            float e0 = zc0 - code0, e1 = zc1 - code1;
            err = e0 * e0 + e1 * e1;
        }
        ulonglong2 cw;
        cw.x = pack2(code0, code0);
        cw.y = pack2(code1, code1);
        *reinterpret_cast<ulonglong2*>(&sC[trow * DDIM + d0]) = cw;
    }

    // Block-reduce squared error -> per-block partial
    #pragma unroll
    for (int o = 16; o > 0; o >>= 1) err += __shfl_down_sync(0xffffffffu, err, o);
    if ((tid & 31) == 0) sRed[tid >> 5] = err;
    __syncthreads();   // also publishes sC for phase 2
    if (tid == 0) {
        float t = 0.f;
        #pragma unroll
        for (int w = 0; w < THREADS / 32; w++) t += sRed[w];
        g_partials[blockIdx.x] = t;
    }

    // ---------------- Phase 2: expand ----------------
    if (tid < EXP_THREADS) {
        const int c0 = tid * 4;
        ulonglong2 wv[DDIM];
        #pragma unroll
        for (int d = 0; d < DDIM; d++)
            wv[d] = *reinterpret_cast<const ulonglong2*>(&We[d * C_IN + c0]);
        ulonglong2 bev = *reinterpret_cast<const ulonglong2*>(&be[c0]);

        const int tok0 = blockIdx.x * TILE;
        int tmax = ntok - tok0;
        if (tmax > TILE) tmax = TILE;

        int t = 0;
        for (; t + 4 <= tmax; t += 4) {
            unsigned long long a[4][2];
            #pragma unroll
            for (int q = 0; q < 4; q++) { a[q][0] = bev.x; a[q][1] = bev.y; }
            #pragma unroll
            for (int d = 0; d < DDIM; d++) {
                #pragma unroll
                for (int q = 0; q < 4; q++) {
                    unsigned long long cd = sC[(t + q) * DDIM + d];  // broadcast
                    a[q][0] = fma2(cd, wv[d].x, a[q][0]);
                    a[q][1] = fma2(cd, wv[d].y, a[q][1]);
                }
            }
            #pragma unroll
            for (int q = 0; q < 4; q++) {
                float4 o;
                unpack2(a[q][0], o.x, o.y);
                unpack2(a[q][1], o.z, o.w);
                *reinterpret_cast<float4*>(
                    &out[(size_t)(tok0 + t + q) * C_IN + c0]) = o;
            }
        }
        for (; t < tmax; t++) {
            unsigned long long a0 = bev.x, a1 = bev.y;
            #pragma unroll
            for (int d = 0; d < DDIM; d++) {
                unsigned long long cd = sC[t * DDIM + d];
                a0 = fma2(cd, wv[d].x, a0);
                a1 = fma2(cd, wv[d].y, a1);
            }
            float4 o;
            unpack2(a0, o.x, o.y);
            unpack2(a1, o.z, o.w);
            *reinterpret_cast<float4*>(&out[(size_t)(tok0 + t) * C_IN + c0]) = o;
        }
    }

    // ---------------- Tail: last block finalizes the error scalar ----------
    if (erridx >= 0) {
        if (tid == 0) {
            __threadfence();  // publish g_partials[bid] before counting
            // wraps to 0 after nblk increments -> self-resetting across replays
            sLast = (atomicInc(&g_done, (unsigned)nblk - 1u) == (unsigned)nblk - 1u);
        }
        __syncthreads();
        if (sLast) {
            float s = 0.f;
            for (int i = tid; i < nblk; i += THREADS) s += g_partials[i];
            #pragma unroll
            for (int o = 16; o > 0; o >>= 1)
                s += __shfl_down_sync(0xffffffffu, s, o);
            if ((tid & 31) == 0) sRed[tid >> 5] = s;
            __syncthreads();
            if (tid == 0) {
                float tot = 0.f;
                #pragma unroll
                for (int w = 0; w < THREADS / 32; w++) tot += sRed[w];
                out[erridx] = tot * errinv;
            }
        }
    }
}

extern "C" void kernel_launch(void* const* d_in, const int* in_sizes, int n_in,
                              void* d_out, int out_size) {
    const float* z  = (const float*)d_in[0];
    const float* u  = (const float*)d_in[1];
    const float* Wc = (const float*)d_in[2];
    const float* bc = (const float*)d_in[3];
    const float* We = (const float*)d_in[4];
    const float* be = (const float*)d_in[5];
    const float* cb = (const float*)d_in[6];
    // d_in[7] = codebook_mask: all-true here (levels == [8]*8), intentionally unused.
    float* out = (float*)d_out;

    const int ntok = in_sizes[0] / C_IN;            // 65536
    const int nblk = (ntok + TILE - 1) / TILE;      // 1024

    long long erridx = (out_size > ntok * C_IN) ? (long long)ntok * C_IN : -1;

    k_fused<<<nblk, THREADS>>>(z, u, Wc, bc, We, be, cb, out, ntok, nblk,
                               erridx, 1.0f / ((float)ntok * (float)DDIM));
}